// round 1
// baseline (speedup 1.0000x reference)
#include <cuda_runtime.h>

// MicroGPT forward, sm_103a. Fixed shapes.
#define NB  16
#define NT  2048
#define NC  16
#define NH  2
#define NHS 8
#define NL  2
#define NV  256
#define NTOK (NB*NT)
#define EPSF 1e-5f
// (1/sqrt(HS)) * log2(e): q is pre-scaled so softmax uses ex2 directly
#define QSCALE 0.5100700982280911f

// Scratch (device globals; no dynamic allocation allowed)
__device__ float g_x[NTOK*NC];
__device__ float g_q[NB*NH*NT*NHS];
__device__ float g_k[NB*NH*NT*NHS];
__device__ float g_v[NB*NH*NT*NHS];
__device__ float g_o[NB*NH*NT*NHS];

__device__ __forceinline__ float ex2f(float x){
    float y; asm("ex2.approx.f32 %0, %1;" : "=f"(y) : "f"(x)); return y;
}

// ---------------------------------------------------------------------------
// 1) x[b,t,:] = tok_emb[idx[b,t],:] + pos_emb[t,:]
// ---------------------------------------------------------------------------
__global__ void embed_kernel(const int* __restrict__ idx,
                             const float* __restrict__ te,
                             const float* __restrict__ pe){
    int tok = blockIdx.x*blockDim.x + threadIdx.x;
    if (tok >= NTOK) return;
    int t  = tok & (NT-1);
    int id = idx[tok];
    const float4* t4 = (const float4*)te + id*4;
    const float4* p4 = (const float4*)pe + t*4;
    float4* x4 = (float4*)g_x + (size_t)tok*4;
    #pragma unroll
    for (int k=0;k<4;k++){
        float4 a=t4[k], b=p4[k];
        x4[k] = make_float4(a.x+b.x, a.y+b.y, a.z+b.z, a.w+b.w);
    }
}

// ---------------------------------------------------------------------------
// 2) h = LN1(x);  q,k,v = h @ W{q,k,v}[head]   (q pre-scaled by QSCALE)
// One thread per token.
// ---------------------------------------------------------------------------
__global__ void qkv_kernel(const float* __restrict__ wq,
                           const float* __restrict__ wk,
                           const float* __restrict__ wv,
                           const float* __restrict__ g1,
                           const float* __restrict__ b1){
    int tok = blockIdx.x*blockDim.x + threadIdx.x;
    if (tok >= NTOK) return;
    int b = tok >> 11;          // / NT
    int t = tok & (NT-1);

    float xr[NC];
    const float4* x4 = (const float4*)g_x + (size_t)tok*4;
    #pragma unroll
    for (int k=0;k<4;k++){
        float4 v=x4[k];
        xr[4*k]=v.x; xr[4*k+1]=v.y; xr[4*k+2]=v.z; xr[4*k+3]=v.w;
    }
    float m=0.f;
    #pragma unroll
    for (int c=0;c<NC;c++) m += xr[c];
    m *= (1.f/NC);
    float var=0.f;
    #pragma unroll
    for (int c=0;c<NC;c++){ float d=xr[c]-m; var += d*d; }
    var *= (1.f/NC);
    float inv = rsqrtf(var + EPSF);
    float h[NC];
    #pragma unroll
    for (int c=0;c<NC;c++) h[c] = (xr[c]-m)*inv*g1[c] + b1[c];

    #pragma unroll
    for (int head=0; head<NH; head++){
        size_t obase = ((size_t)(b*NH+head)*NT + t)*NHS;
        const float* Wq = wq + head*NC*NHS;
        const float* Wk = wk + head*NC*NHS;
        const float* Wv = wv + head*NC*NHS;
        float aq[NHS], ak[NHS], av[NHS];
        #pragma unroll
        for (int s=0;s<NHS;s++){ aq[s]=0.f; ak[s]=0.f; av[s]=0.f; }
        #pragma unroll
        for (int c=0;c<NC;c++){
            float hc = h[c];
            #pragma unroll
            for (int s=0;s<NHS;s++){
                aq[s] += hc*Wq[c*NHS+s];
                ak[s] += hc*Wk[c*NHS+s];
                av[s] += hc*Wv[c*NHS+s];
            }
        }
        #pragma unroll
        for (int s=0;s<NHS;s++){
            g_q[obase+s] = aq[s]*QSCALE;
            g_k[obase+s] = ak[s];
            g_v[obase+s] = av[s];
        }
    }
}

// ---------------------------------------------------------------------------
// 3) Causal attention, flash-style. One thread per query row; key tiles of 256
//    staged in smem. Scores are O(0.1) here, so softmax without max subtraction
//    is exact math (just "less stable", irrelevant at this magnitude).
// grid = (B*H, T/256), block = 256
// ---------------------------------------------------------------------------
__global__ void __launch_bounds__(256) attn_kernel(){
    int bh  = blockIdx.x;
    int qb  = blockIdx.y;
    int tid = threadIdx.x;
    int t   = qb*256 + tid;

    const float4* kg = (const float4*)g_k + (size_t)bh*NT*2;  // 2 float4 per key
    const float4* vg = (const float4*)g_v + (size_t)bh*NT*2;

    float q[NHS];
    const float* qp = g_q + ((size_t)bh*NT + t)*NHS;
    #pragma unroll
    for (int i=0;i<NHS;i++) q[i]=qp[i];

    __shared__ float4 ks[512];
    __shared__ float4 vs[512];

    float den = 0.f;
    float acc[NHS];
    #pragma unroll
    for (int i=0;i<NHS;i++) acc[i]=0.f;

    for (int kt=0; kt<=qb; kt++){
        int base4 = kt*512;              // float4 offset of tile start
        ks[tid]      = kg[base4 + tid];
        ks[tid+256]  = kg[base4 + tid + 256];
        vs[tid]      = vg[base4 + tid];
        vs[tid+256]  = vg[base4 + tid + 256];
        __syncthreads();

        int jmax = (kt==qb) ? (tid+1) : 256;
        #pragma unroll 4
        for (int j=0; j<jmax; j++){
            float4 ka = ks[2*j], kb = ks[2*j+1];
            float s = q[0]*ka.x + q[1]*ka.y + q[2]*ka.z + q[3]*ka.w
                    + q[4]*kb.x + q[5]*kb.y + q[6]*kb.z + q[7]*kb.w;
            float p = ex2f(s);
            den += p;
            float4 va = vs[2*j], vb = vs[2*j+1];
            acc[0]+=p*va.x; acc[1]+=p*va.y; acc[2]+=p*va.z; acc[3]+=p*va.w;
            acc[4]+=p*vb.x; acc[5]+=p*vb.y; acc[6]+=p*vb.z; acc[7]+=p*vb.w;
        }
        __syncthreads();
    }

    float invd = 1.f/den;
    float* op = g_o + ((size_t)bh*NT + t)*NHS;
    #pragma unroll
    for (int i=0;i<NHS;i++) op[i] = acc[i]*invd;
}

// ---------------------------------------------------------------------------
// 4) x += concat(o) @ Wo^T;  h = LN2(x);  x += relu(h @ W1^T) @ W2^T
// One thread per token.
// ---------------------------------------------------------------------------
__global__ void post_kernel(const float* __restrict__ wo,
                            const float* __restrict__ g2,
                            const float* __restrict__ b2,
                            const float* __restrict__ w1,
                            const float* __restrict__ w2){
    int tok = blockIdx.x*blockDim.x + threadIdx.x;
    if (tok >= NTOK) return;
    int b = tok >> 11;
    int t = tok & (NT-1);

    float o16[NC];
    const float* o0 = g_o + ((size_t)(b*NH+0)*NT + t)*NHS;
    const float* o1 = g_o + ((size_t)(b*NH+1)*NT + t)*NHS;
    #pragma unroll
    for (int s=0;s<NHS;s++){ o16[s]=o0[s]; o16[NHS+s]=o1[s]; }

    float xr[NC];
    const float4* x4 = (const float4*)g_x + (size_t)tok*4;
    #pragma unroll
    for (int k=0;k<4;k++){
        float4 v=x4[k];
        xr[4*k]=v.x; xr[4*k+1]=v.y; xr[4*k+2]=v.z; xr[4*k+3]=v.w;
    }

    // Wo projection + residual
    #pragma unroll
    for (int i=0;i<NC;i++){
        float s=0.f;
        #pragma unroll
        for (int c=0;c<NC;c++) s += o16[c]*wo[i*NC+c];
        xr[i] += s;
    }

    // LN2
    float m=0.f;
    #pragma unroll
    for (int c=0;c<NC;c++) m += xr[c];
    m *= (1.f/NC);
    float var=0.f;
    #pragma unroll
    for (int c=0;c<NC;c++){ float d=xr[c]-m; var += d*d; }
    var *= (1.f/NC);
    float inv = rsqrtf(var + EPSF);
    float h[NC];
    #pragma unroll
    for (int c=0;c<NC;c++) h[c] = (xr[c]-m)*inv*g2[c] + b2[c];

    // MLP: y_j = relu(h . w1[j,:]); x_i += y_j * w2[i, j]
    #pragma unroll 4
    for (int j=0;j<4*NC;j++){
        float y=0.f;
        #pragma unroll
        for (int c=0;c<NC;c++) y += h[c]*w1[j*NC+c];
        y = fmaxf(y, 0.f);
        #pragma unroll
        for (int i=0;i<NC;i++) xr[i] += y*w2[i*4*NC + j];
    }

    float4* xo = (float4*)g_x + (size_t)tok*4;
    #pragma unroll
    for (int k=0;k<4;k++)
        xo[k] = make_float4(xr[4*k], xr[4*k+1], xr[4*k+2], xr[4*k+3]);
}

// ---------------------------------------------------------------------------
// 5) h = LNf(x); logits = h @ tok_emb^T.  Block per token, thread per vocab id.
// ---------------------------------------------------------------------------
__global__ void __launch_bounds__(NV) head_kernel(const float* __restrict__ te,
                                                  const float* __restrict__ gf,
                                                  const float* __restrict__ bf,
                                                  float* __restrict__ out){
    int tok = blockIdx.x;
    int v   = threadIdx.x;
    __shared__ float hs[NC];

    if (threadIdx.x < 32){
        int lane = threadIdx.x;
        float val = (lane < NC) ? g_x[(size_t)tok*NC + lane] : 0.f;
        float s = val;
        #pragma unroll
        for (int o=16;o>0;o>>=1) s += __shfl_xor_sync(0xffffffffu, s, o);
        float m = s * (1.f/NC);
        float d = (lane < NC) ? (val - m) : 0.f;
        float vv = d*d;
        #pragma unroll
        for (int o=16;o>0;o>>=1) vv += __shfl_xor_sync(0xffffffffu, vv, o);
        float inv = rsqrtf(vv*(1.f/NC) + EPSF);
        if (lane < NC) hs[lane] = d*inv*gf[lane] + bf[lane];
    }
    __syncthreads();

    float4 h0 = *(const float4*)&hs[0];
    float4 h1 = *(const float4*)&hs[4];
    float4 h2 = *(const float4*)&hs[8];
    float4 h3 = *(const float4*)&hs[12];
    const float4* tr = (const float4*)te + v*4;
    float4 t0 = tr[0], t1 = tr[1], t2 = tr[2], t3 = tr[3];
    float logit =
        h0.x*t0.x + h0.y*t0.y + h0.z*t0.z + h0.w*t0.w +
        h1.x*t1.x + h1.y*t1.y + h1.z*t1.z + h1.w*t1.w +
        h2.x*t2.x + h2.y*t2.y + h2.z*t2.z + h2.w*t2.w +
        h3.x*t3.x + h3.y*t3.y + h3.z*t3.z + h3.w*t3.w;
    out[(size_t)tok*NV + v] = logit;
}

// ---------------------------------------------------------------------------
extern "C" void kernel_launch(void* const* d_in, const int* in_sizes, int n_in,
                              void* d_out, int out_size){
    const int*   idx  = (const int*)  d_in[0];
    const float* te   = (const float*)d_in[1];
    const float* pe   = (const float*)d_in[2];
    const float* wq   = (const float*)d_in[3];
    const float* wk   = (const float*)d_in[4];
    const float* wv   = (const float*)d_in[5];
    const float* wo   = (const float*)d_in[6];
    const float* ln1g = (const float*)d_in[7];
    const float* ln1b = (const float*)d_in[8];
    const float* ln2g = (const float*)d_in[9];
    const float* ln2b = (const float*)d_in[10];
    const float* w1   = (const float*)d_in[11];
    const float* w2   = (const float*)d_in[12];
    const float* lnfg = (const float*)d_in[13];
    const float* lnfb = (const float*)d_in[14];
    float* out = (float*)d_out;

    const int TPB = 256;
    const int TOKB = NTOK/TPB;     // 128 blocks

    embed_kernel<<<TOKB, TPB>>>(idx, te, pe);
    for (int l=0; l<NL; l++){
        qkv_kernel<<<TOKB, TPB>>>(wq + l*NH*NC*NHS, wk + l*NH*NC*NHS,
                                  wv + l*NH*NC*NHS, ln1g + l*NC, ln1b + l*NC);
        dim3 ag(NB*NH, NT/256);
        attn_kernel<<<ag, 256>>>();
        post_kernel<<<TOKB, TPB>>>(wo + l*NC*NC, ln2g + l*NC, ln2b + l*NC,
                                   w1 + l*4*NC*NC, w2 + l*4*NC*NC);
    }
    head_kernel<<<NTOK, NV>>>(te, lnfg, lnfb, out);
}

// round 3
// speedup vs baseline: 2.5033x; 2.5033x over previous
#include <cuda_runtime.h>

// MicroGPT forward, sm_103a. Fixed shapes.
#define NB  16
#define NT  2048
#define NC  16
#define NH  2
#define NHS 8
#define NL  2
#define NV  256
#define NTOK (NB*NT)
#define EPSF 1e-5f
// (1/sqrt(HS)) * log2(e): q pre-scaled so softmax uses ex2 directly
#define QSCALE 0.5100700982280911f

typedef unsigned long long u64;

// Scratch (device globals; no dynamic allocation allowed)
__device__ float g_x[NTOK*NC];
__device__ float g_q[NB*NH*NT*NHS];
__device__ float g_k[NB*NH*NT*NHS];
__device__ float g_v[NB*NH*NT*NHS];
__device__ float g_o[NB*NH*NT*NHS];

__device__ __forceinline__ float ex2f(float x){
    float y; asm("ex2.approx.f32 %0, %1;" : "=f"(y) : "f"(x)); return y;
}
__device__ __forceinline__ u64 fma2(u64 a, u64 b, u64 c){
    u64 d; asm("fma.rn.f32x2 %0, %1, %2, %3;" : "=l"(d) : "l"(a), "l"(b), "l"(c)); return d;
}
__device__ __forceinline__ u64 mul2(u64 a, u64 b){
    u64 d; asm("mul.rn.f32x2 %0, %1, %2;" : "=l"(d) : "l"(a), "l"(b)); return d;
}
__device__ __forceinline__ u64 pack2(float lo, float hi){
    u64 r; asm("mov.b64 %0, {%1, %2};" : "=l"(r) : "f"(lo), "f"(hi)); return r;
}
__device__ __forceinline__ float2 unpack2(u64 v){
    float lo, hi; asm("mov.b64 {%0, %1}, %2;" : "=f"(lo), "=f"(hi) : "l"(v));
    return make_float2(lo, hi);
}

// ---------------------------------------------------------------------------
// 1) x[b,t,:] = tok_emb[idx[b,t],:] + pos_emb[t,:]
// ---------------------------------------------------------------------------
__global__ void embed_kernel(const int* __restrict__ idx,
                             const float* __restrict__ te,
                             const float* __restrict__ pe){
    int tok = blockIdx.x*blockDim.x + threadIdx.x;
    if (tok >= NTOK) return;
    int t  = tok & (NT-1);
    int id = idx[tok];
    const float4* t4 = (const float4*)te + id*4;
    const float4* p4 = (const float4*)pe + t*4;
    float4* x4 = (float4*)g_x + (size_t)tok*4;
    #pragma unroll
    for (int k=0;k<4;k++){
        float4 a=t4[k], b=p4[k];
        x4[k] = make_float4(a.x+b.x, a.y+b.y, a.z+b.z, a.w+b.w);
    }
}

// ---------------------------------------------------------------------------
// 2) h = LN1(x);  q,k,v = h @ W{q,k,v}[head]  (q pre-scaled). Weights in smem.
// ---------------------------------------------------------------------------
__global__ void __launch_bounds__(128) qkv_kernel(const float* __restrict__ wq,
                           const float* __restrict__ wk,
                           const float* __restrict__ wv,
                           const float* __restrict__ g1,
                           const float* __restrict__ b1){
    __shared__ float sq[NH*NC*NHS], sk[NH*NC*NHS], sv[NH*NC*NHS];
    __shared__ float sg[NC], sb[NC];
    int tid = threadIdx.x;
    for (int i=tid; i<NH*NC*NHS; i+=128){ sq[i]=wq[i]; sk[i]=wk[i]; sv[i]=wv[i]; }
    if (tid < NC){ sg[tid]=g1[tid]; sb[tid]=b1[tid]; }
    __syncthreads();

    int tok = blockIdx.x*128 + tid;
    int b = tok >> 11;
    int t = tok & (NT-1);

    float xr[NC];
    const float4* x4 = (const float4*)g_x + (size_t)tok*4;
    #pragma unroll
    for (int k=0;k<4;k++){
        float4 v=x4[k];
        xr[4*k]=v.x; xr[4*k+1]=v.y; xr[4*k+2]=v.z; xr[4*k+3]=v.w;
    }
    float m=0.f;
    #pragma unroll
    for (int c=0;c<NC;c++) m += xr[c];
    m *= (1.f/NC);
    float var=0.f;
    #pragma unroll
    for (int c=0;c<NC;c++){ float d=xr[c]-m; var += d*d; }
    var *= (1.f/NC);
    float inv = rsqrtf(var + EPSF);
    float h[NC];
    #pragma unroll
    for (int c=0;c<NC;c++) h[c] = (xr[c]-m)*inv*sg[c] + sb[c];

    #pragma unroll
    for (int head=0; head<NH; head++){
        size_t obase = ((size_t)(b*NH+head)*NT + t)*NHS;
        const float* Wq = sq + head*NC*NHS;
        const float* Wk = sk + head*NC*NHS;
        const float* Wv = sv + head*NC*NHS;
        float aq[NHS], ak[NHS], av[NHS];
        #pragma unroll
        for (int s=0;s<NHS;s++){ aq[s]=0.f; ak[s]=0.f; av[s]=0.f; }
        #pragma unroll
        for (int c=0;c<NC;c++){
            float hc = h[c];
            #pragma unroll
            for (int s=0;s<NHS;s++){
                aq[s] += hc*Wq[c*NHS+s];
                ak[s] += hc*Wk[c*NHS+s];
                av[s] += hc*Wv[c*NHS+s];
            }
        }
        #pragma unroll
        for (int s=0;s<NHS;s++){
            g_q[obase+s] = aq[s]*QSCALE;
            g_k[obase+s] = ak[s];
            g_v[obase+s] = av[s];
        }
    }
}

// ---------------------------------------------------------------------------
// 3) Causal attention, balanced tile pairing.
//    16 query tiles of 128 rows per (b,h). Block (512 thr) covers tiles
//    {y, 7-y, 8+y, 15-y} -> exactly 34 tile-units of work per block.
//    grid = (B*H=32, 4) = 128 blocks = one balanced wave.
//    Inner loop in packed f32x2.
// ---------------------------------------------------------------------------
__global__ void __launch_bounds__(512) attn_kernel(){
    int bh   = blockIdx.x;
    int y    = blockIdx.y;              // 0..3
    int tid  = threadIdx.x;
    int quad = tid >> 7;                // 0..3
    int lane = tid & 127;

    int tq;                              // query tile index for this quarter
    switch (quad){
        case 0: tq = y;      break;
        case 1: tq = 7-y;    break;
        case 2: tq = 8+y;    break;
        default: tq = 15-y;  break;
    }
    int t = tq*128 + lane;

    const float4* kg = (const float4*)g_k + (size_t)bh*NT*2;
    const float4* vg = (const float4*)g_v + (size_t)bh*NT*2;

    // q packed as 4 x f32x2
    const ulonglong2* qg = (const ulonglong2*)(g_q + ((size_t)bh*NT + t)*NHS);
    ulonglong2 qA = qg[0], qB = qg[1];
    u64 q01 = qA.x, q23 = qA.y, q45 = qB.x, q67 = qB.y;

    __shared__ ulonglong2 ks[256];   // 128 keys x 32B
    __shared__ ulonglong2 vs[256];

    float den = 0.f;
    u64 a01 = 0, a23 = 0, a45 = 0, a67 = 0;   // fp32 pairs, 0.0f bit pattern

    int ktmax = 15 - y;   // max tile any quarter needs
    for (int kt=0; kt<=ktmax; kt++){
        // stage 128 keys (k and v): 512 float4 loads, one per thread
        {
            int i = tid;
            if (i < 256) ((float4*)ks)[i] = kg[kt*256 + i];
            else         ((float4*)vs)[i-256] = vg[kt*256 + (i-256)];
        }
        __syncthreads();

        if (kt <= tq){
            int jmax = (kt==tq) ? (lane+1) : 128;
            #pragma unroll 2
            for (int j=0; j<jmax; j++){
                ulonglong2 ka = ks[2*j], kb = ks[2*j+1];
                u64 s2 = mul2(q01, ka.x);
                s2 = fma2(q23, ka.y, s2);
                s2 = fma2(q45, kb.x, s2);
                s2 = fma2(q67, kb.y, s2);
                float2 sp = unpack2(s2);
                float p = ex2f(sp.x + sp.y);
                den += p;
                u64 pp = pack2(p, p);
                ulonglong2 va = vs[2*j], vb = vs[2*j+1];
                a01 = fma2(pp, va.x, a01);
                a23 = fma2(pp, va.y, a23);
                a45 = fma2(pp, vb.x, a45);
                a67 = fma2(pp, vb.y, a67);
            }
        }
        __syncthreads();
    }

    float invd = 1.f/den;
    float2 r0 = unpack2(a01), r1 = unpack2(a23), r2 = unpack2(a45), r3 = unpack2(a67);
    float4* op = (float4*)(g_o + ((size_t)bh*NT + t)*NHS);
    op[0] = make_float4(r0.x*invd, r0.y*invd, r1.x*invd, r1.y*invd);
    op[1] = make_float4(r2.x*invd, r2.y*invd, r3.x*invd, r3.y*invd);
}

// ---------------------------------------------------------------------------
// 4) x += concat(o) @ Wo^T;  h = LN2(x);  x += relu(h @ W1^T) @ W2^T
//    Weights staged in smem (w2 transposed for contiguous column access).
// ---------------------------------------------------------------------------
__global__ void __launch_bounds__(128) post_kernel(const float* __restrict__ wo,
                            const float* __restrict__ g2,
                            const float* __restrict__ b2,
                            const float* __restrict__ w1,
                            const float* __restrict__ w2){
    __shared__ float s_wo[NC*NC];
    __shared__ float s_w1[4*NC*NC];
    __shared__ float s_w2[4*NC*NC];   // [j][i] = w2[i][j]
    __shared__ float sg[NC], sb[NC];
    int tid = threadIdx.x;
    for (int i=tid; i<NC*NC; i+=128) s_wo[i] = wo[i];
    for (int i=tid; i<4*NC*NC; i+=128) s_w1[i] = w1[i];
    for (int idx=tid; idx<4*NC*NC; idx+=128){
        int j = idx >> 4, i = idx & 15;
        s_w2[idx] = w2[i*(4*NC) + j];
    }
    if (tid < NC){ sg[tid]=g2[tid]; sb[tid]=b2[tid]; }
    __syncthreads();

    int tok = blockIdx.x*128 + tid;
    int b = tok >> 11;
    int t = tok & (NT-1);

    float o16[NC];
    const float* o0 = g_o + ((size_t)(b*NH+0)*NT + t)*NHS;
    const float* o1 = g_o + ((size_t)(b*NH+1)*NT + t)*NHS;
    #pragma unroll
    for (int s=0;s<NHS;s++){ o16[s]=o0[s]; o16[NHS+s]=o1[s]; }

    float xr[NC];
    const float4* x4 = (const float4*)g_x + (size_t)tok*4;
    #pragma unroll
    for (int k=0;k<4;k++){
        float4 v=x4[k];
        xr[4*k]=v.x; xr[4*k+1]=v.y; xr[4*k+2]=v.z; xr[4*k+3]=v.w;
    }

    // Wo projection + residual
    #pragma unroll
    for (int i=0;i<NC;i++){
        float s=0.f;
        #pragma unroll
        for (int c=0;c<NC;c++) s += o16[c]*s_wo[i*NC+c];
        xr[i] += s;
    }

    // LN2
    float m=0.f;
    #pragma unroll
    for (int c=0;c<NC;c++) m += xr[c];
    m *= (1.f/NC);
    float var=0.f;
    #pragma unroll
    for (int c=0;c<NC;c++){ float d=xr[c]-m; var += d*d; }
    var *= (1.f/NC);
    float inv = rsqrtf(var + EPSF);
    float h[NC];
    #pragma unroll
    for (int c=0;c<NC;c++) h[c] = (xr[c]-m)*inv*sg[c] + sb[c];

    // MLP
    #pragma unroll 4
    for (int j=0;j<4*NC;j++){
        float yv=0.f;
        #pragma unroll
        for (int c=0;c<NC;c++) yv += h[c]*s_w1[j*NC+c];
        yv = fmaxf(yv, 0.f);
        #pragma unroll
        for (int i=0;i<NC;i++) xr[i] += yv*s_w2[j*NC+i];
    }

    float4* xo = (float4*)g_x + (size_t)tok*4;
    #pragma unroll
    for (int k=0;k<4;k++)
        xo[k] = make_float4(xr[4*k], xr[4*k+1], xr[4*k+2], xr[4*k+3]);
}

// ---------------------------------------------------------------------------
// 5) h = LNf(x); logits = h @ tok_emb^T.
//    Block = 256 threads = 256 vocab cols, covers 8 tokens: te row registered
//    once per thread, reused across the 8 tokens.
// ---------------------------------------------------------------------------
__global__ void __launch_bounds__(NV) head_kernel(const float* __restrict__ te,
                                                  const float* __restrict__ gf,
                                                  const float* __restrict__ bf,
                                                  float* __restrict__ out){
    int tid  = threadIdx.x;
    int warp = tid >> 5, lane = tid & 31;
    int tok0 = blockIdx.x * 8;
    __shared__ float hs[8][NC];

    // warp w computes LN of token tok0+w
    {
        int tok = tok0 + warp;
        float val = (lane < NC) ? g_x[(size_t)tok*NC + lane] : 0.f;
        float s = val;
        #pragma unroll
        for (int o=16;o>0;o>>=1) s += __shfl_xor_sync(0xffffffffu, s, o);
        float m = s * (1.f/NC);
        float d = (lane < NC) ? (val - m) : 0.f;
        float vv = d*d;
        #pragma unroll
        for (int o=16;o>0;o>>=1) vv += __shfl_xor_sync(0xffffffffu, vv, o);
        float inv = rsqrtf(vv*(1.f/NC) + EPSF);
        if (lane < NC) hs[warp][lane] = d*inv*gf[lane] + bf[lane];
    }
    __syncthreads();

    int v = tid;
    const float4* tr = (const float4*)te + v*4;
    float4 t0 = tr[0], t1 = tr[1], t2 = tr[2], t3 = tr[3];

    #pragma unroll
    for (int k=0;k<8;k++){
        float4 h0 = *(const float4*)&hs[k][0];
        float4 h1 = *(const float4*)&hs[k][4];
        float4 h2 = *(const float4*)&hs[k][8];
        float4 h3 = *(const float4*)&hs[k][12];
        float logit =
            h0.x*t0.x + h0.y*t0.y + h0.z*t0.z + h0.w*t0.w +
            h1.x*t1.x + h1.y*t1.y + h1.z*t1.z + h1.w*t1.w +
            h2.x*t2.x + h2.y*t2.y + h2.z*t2.z + h2.w*t2.w +
            h3.x*t3.x + h3.y*t3.y + h3.z*t3.z + h3.w*t3.w;
        out[(size_t)(tok0+k)*NV + v] = logit;
    }
}

// ---------------------------------------------------------------------------
extern "C" void kernel_launch(void* const* d_in, const int* in_sizes, int n_in,
                              void* d_out, int out_size){
    const int*   idx  = (const int*)  d_in[0];
    const float* te   = (const float*)d_in[1];
    const float* pe   = (const float*)d_in[2];
    const float* wq   = (const float*)d_in[3];
    const float* wk   = (const float*)d_in[4];
    const float* wv   = (const float*)d_in[5];
    const float* wo   = (const float*)d_in[6];
    const float* ln1g = (const float*)d_in[7];
    const float* ln1b = (const float*)d_in[8];
    const float* ln2g = (const float*)d_in[9];
    const float* ln2b = (const float*)d_in[10];
    const float* w1   = (const float*)d_in[11];
    const float* w2   = (const float*)d_in[12];
    const float* lnfg = (const float*)d_in[13];
    const float* lnfb = (const float*)d_in[14];
    float* out = (float*)d_out;

    embed_kernel<<<NTOK/256, 256>>>(idx, te, pe);
    for (int l=0; l<NL; l++){
        qkv_kernel<<<NTOK/128, 128>>>(wq + l*NH*NC*NHS, wk + l*NH*NC*NHS,
                                      wv + l*NH*NC*NHS, ln1g + l*NC, ln1b + l*NC);
        dim3 ag(NB*NH, 4);
        attn_kernel<<<ag, 512>>>();
        post_kernel<<<NTOK/128, 128>>>(wo + l*NC*NC, ln2g + l*NC, ln2b + l*NC,
                                       w1 + l*4*NC*NC, w2 + l*4*NC*NC);
    }
    head_kernel<<<NTOK/8, NV>>>(te, lnfg, lnfb, out);
}

// round 5
// speedup vs baseline: 2.8395x; 1.1343x over previous
#include <cuda_runtime.h>

// MicroGPT forward, sm_103a. Fixed shapes.
#define NB  16
#define NT  2048
#define NC  16
#define NH  2
#define NHS 8
#define NL  2
#define NV  256
#define NTOK (NB*NT)
#define EPSF 1e-5f
// (1/sqrt(HS)) * log2(e): q pre-scaled so softmax uses ex2 directly
#define QSCALE 0.5100700982280911f

typedef unsigned long long u64;

// Scratch (device globals; no dynamic allocation allowed)
__device__ float g_x[NTOK*NC];
__device__ float g_q[NB*NH*NT*NHS];
__device__ float g_k[NB*NH*NT*NHS];
__device__ float g_v[NB*NH*NT*NHS];
__device__ float g_o[NB*NH*NT*NHS];

__device__ __forceinline__ float ex2f(float x){
    float y; asm("ex2.approx.f32 %0, %1;" : "=f"(y) : "f"(x)); return y;
}
__device__ __forceinline__ u64 fma2(u64 a, u64 b, u64 c){
    u64 d; asm("fma.rn.f32x2 %0, %1, %2, %3;" : "=l"(d) : "l"(a), "l"(b), "l"(c)); return d;
}
__device__ __forceinline__ u64 mul2(u64 a, u64 b){
    u64 d; asm("mul.rn.f32x2 %0, %1, %2;" : "=l"(d) : "l"(a), "l"(b)); return d;
}
__device__ __forceinline__ u64 pack2(float lo, float hi){
    u64 r; asm("mov.b64 %0, {%1, %2};" : "=l"(r) : "f"(lo), "f"(hi)); return r;
}
__device__ __forceinline__ float2 unpack2(u64 v){
    float lo, hi; asm("mov.b64 {%0, %1}, %2;" : "=f"(lo), "=f"(hi) : "l"(v));
    return make_float2(lo, hi);
}

// ---------------------------------------------------------------------------
// 1) h = LN1(x); q,k,v = h @ W (q pre-scaled). Layer 0 fuses the embedding.
// ---------------------------------------------------------------------------
__global__ void __launch_bounds__(128) qkv_kernel(const float* __restrict__ wq,
                           const float* __restrict__ wk,
                           const float* __restrict__ wv,
                           const float* __restrict__ g1,
                           const float* __restrict__ b1,
                           const int*   __restrict__ idx,
                           const float* __restrict__ te,
                           const float* __restrict__ pe,
                           int fuse_embed){
    __shared__ float sq[NH*NC*NHS], sk[NH*NC*NHS], sv[NH*NC*NHS];
    __shared__ float sg[NC], sb[NC];
    int tid = threadIdx.x;
    for (int i=tid; i<NH*NC*NHS; i+=128){ sq[i]=wq[i]; sk[i]=wk[i]; sv[i]=wv[i]; }
    if (tid < NC){ sg[tid]=g1[tid]; sb[tid]=b1[tid]; }
    __syncthreads();

    int tok = blockIdx.x*128 + tid;
    int b = tok >> 11;
    int t = tok & (NT-1);

    float xr[NC];
    if (fuse_embed){
        int id = idx[tok];
        const float4* t4 = (const float4*)te + id*4;
        const float4* p4 = (const float4*)pe + t*4;
        float4* xo = (float4*)g_x + (size_t)tok*4;
        #pragma unroll
        for (int k=0;k<4;k++){
            float4 aa=t4[k], bb=p4[k];
            float4 r = make_float4(aa.x+bb.x, aa.y+bb.y, aa.z+bb.z, aa.w+bb.w);
            xo[k] = r;
            xr[4*k]=r.x; xr[4*k+1]=r.y; xr[4*k+2]=r.z; xr[4*k+3]=r.w;
        }
    } else {
        const float4* x4 = (const float4*)g_x + (size_t)tok*4;
        #pragma unroll
        for (int k=0;k<4;k++){
            float4 v=x4[k];
            xr[4*k]=v.x; xr[4*k+1]=v.y; xr[4*k+2]=v.z; xr[4*k+3]=v.w;
        }
    }

    float m=0.f;
    #pragma unroll
    for (int c=0;c<NC;c++) m += xr[c];
    m *= (1.f/NC);
    float var=0.f;
    #pragma unroll
    for (int c=0;c<NC;c++){ float d=xr[c]-m; var += d*d; }
    var *= (1.f/NC);
    float inv = rsqrtf(var + EPSF);
    float h[NC];
    #pragma unroll
    for (int c=0;c<NC;c++) h[c] = (xr[c]-m)*inv*sg[c] + sb[c];

    #pragma unroll
    for (int head=0; head<NH; head++){
        size_t obase = ((size_t)(b*NH+head)*NT + t)*NHS;
        const float* Wq = sq + head*NC*NHS;
        const float* Wk = sk + head*NC*NHS;
        const float* Wv = sv + head*NC*NHS;
        float aq[NHS], ak[NHS], av[NHS];
        #pragma unroll
        for (int s=0;s<NHS;s++){ aq[s]=0.f; ak[s]=0.f; av[s]=0.f; }
        #pragma unroll
        for (int c=0;c<NC;c++){
            float hc = h[c];
            #pragma unroll
            for (int s=0;s<NHS;s++){
                aq[s] += hc*Wq[c*NHS+s];
                ak[s] += hc*Wk[c*NHS+s];
                av[s] += hc*Wv[c*NHS+s];
            }
        }
        #pragma unroll
        for (int s=0;s<NHS;s++){
            g_q[obase+s] = aq[s]*QSCALE;
            g_k[obase+s] = ak[s];
            g_v[obase+s] = av[s];
        }
    }
}

// ---------------------------------------------------------------------------
// 2) Causal attention. Dual-query per thread: tiles {a, 15-a} -> every thread
//    does exactly 17 tile-units of key traversal. grid=(32,4), block=256.
//    half = tid>>7 selects a = 2*y + half.
// ---------------------------------------------------------------------------
__global__ void __launch_bounds__(256) attn_kernel(){
    int bh   = blockIdx.x;
    int y    = blockIdx.y;              // 0..3
    int tid  = threadIdx.x;
    int half = tid >> 7;                // 0..1
    int lane = tid & 127;
    int a = y*2 + half;                 // 0..7
    int b = 15 - a;                     // 8..15

    const float4* kg = (const float4*)g_k + (size_t)bh*NT*2;
    const float4* vg = (const float4*)g_v + (size_t)bh*NT*2;

    int tA = a*128 + lane;
    int tB = b*128 + lane;
    const ulonglong2* qga = (const ulonglong2*)(g_q + ((size_t)bh*NT + tA)*NHS);
    ulonglong2 qa0 = qga[0], qa1 = qga[1];
    const ulonglong2* qgb = (const ulonglong2*)(g_q + ((size_t)bh*NT + tB)*NHS);
    ulonglong2 qb0 = qgb[0], qb1 = qgb[1];

    __shared__ ulonglong2 ks[256];   // 128 keys x 32B
    __shared__ ulonglong2 vs[256];

    float denA = 0.f, denB = 0.f;
    u64 aA0=0,aA1=0,aA2=0,aA3=0;
    u64 aB0=0,aB1=0,aB2=0,aB3=0;

    int ktmax = 15 - 2*y;               // covers b for half=0
    for (int kt=0; kt<=ktmax; kt++){
        ((float4*)ks)[tid] = kg[kt*256 + tid];
        ((float4*)vs)[tid] = vg[kt*256 + tid];
        __syncthreads();

        if (kt <= a){
            // dual: A (masked on diag tile) + B full
            bool diag = (kt == a);
            #pragma unroll 2
            for (int j=0; j<128; j++){
                ulonglong2 k0 = ks[2*j], k1 = ks[2*j+1];
                u64 sa = mul2(qa0.x, k0.x);
                sa = fma2(qa0.y, k0.y, sa);
                sa = fma2(qa1.x, k1.x, sa);
                sa = fma2(qa1.y, k1.y, sa);
                u64 sb = mul2(qb0.x, k0.x);
                sb = fma2(qb0.y, k0.y, sb);
                sb = fma2(qb1.x, k1.x, sb);
                sb = fma2(qb1.y, k1.y, sb);
                float2 fa = unpack2(sa), fb = unpack2(sb);
                float pA = ex2f(fa.x + fa.y);
                float pB = ex2f(fb.x + fb.y);
                if (diag && j > lane) pA = 0.f;
                denA += pA; denB += pB;
                u64 ppA = pack2(pA,pA), ppB = pack2(pB,pB);
                ulonglong2 v0 = vs[2*j], v1 = vs[2*j+1];
                aA0 = fma2(ppA, v0.x, aA0);
                aA1 = fma2(ppA, v0.y, aA1);
                aA2 = fma2(ppA, v1.x, aA2);
                aA3 = fma2(ppA, v1.y, aA3);
                aB0 = fma2(ppB, v0.x, aB0);
                aB1 = fma2(ppB, v0.y, aB1);
                aB2 = fma2(ppB, v1.x, aB2);
                aB3 = fma2(ppB, v1.y, aB3);
            }
        } else if (kt <= b){
            int jmax = (kt==b) ? (lane+1) : 128;
            #pragma unroll 4
            for (int j=0; j<jmax; j++){
                ulonglong2 k0 = ks[2*j], k1 = ks[2*j+1];
                u64 sb = mul2(qb0.x, k0.x);
                sb = fma2(qb0.y, k0.y, sb);
                sb = fma2(qb1.x, k1.x, sb);
                sb = fma2(qb1.y, k1.y, sb);
                float2 fb = unpack2(sb);
                float pB = ex2f(fb.x + fb.y);
                denB += pB;
                u64 pp = pack2(pB,pB);
                ulonglong2 v0 = vs[2*j], v1 = vs[2*j+1];
                aB0 = fma2(pp, v0.x, aB0);
                aB1 = fma2(pp, v0.y, aB1);
                aB2 = fma2(pp, v1.x, aB2);
                aB3 = fma2(pp, v1.y, aB3);
            }
        }
        __syncthreads();
    }

    float ia = 1.f/denA, ib = 1.f/denB;
    {
        float2 r0=unpack2(aA0), r1=unpack2(aA1), r2=unpack2(aA2), r3=unpack2(aA3);
        float4* op = (float4*)(g_o + ((size_t)bh*NT + tA)*NHS);
        op[0] = make_float4(r0.x*ia, r0.y*ia, r1.x*ia, r1.y*ia);
        op[1] = make_float4(r2.x*ia, r2.y*ia, r3.x*ia, r3.y*ia);
    }
    {
        float2 r0=unpack2(aB0), r1=unpack2(aB1), r2=unpack2(aB2), r3=unpack2(aB3);
        float4* op = (float4*)(g_o + ((size_t)bh*NT + tB)*NHS);
        op[0] = make_float4(r0.x*ib, r0.y*ib, r1.x*ib, r1.y*ib);
        op[1] = make_float4(r2.x*ib, r2.y*ib, r3.x*ib, r3.y*ib);
    }
}

// ---------------------------------------------------------------------------
// 3) x += concat(o) @ Wo^T;  h = LN2(x);  x += relu(h @ W1^T) @ W2^T
//    Weights in smem; Wo and MLP loops in packed f32x2.
// ---------------------------------------------------------------------------
__global__ void __launch_bounds__(128) post_kernel(const float* __restrict__ wo,
                            const float* __restrict__ g2,
                            const float* __restrict__ b2,
                            const float* __restrict__ w1,
                            const float* __restrict__ w2){
    __shared__ __align__(16) float s_wo[NC*NC];
    __shared__ __align__(16) float s_w1[4*NC*NC];
    __shared__ __align__(16) float s_w2[4*NC*NC];   // [j][i] = w2[i][j]
    __shared__ float sg[NC], sb[NC];
    int tid = threadIdx.x;
    for (int i=tid; i<NC*NC; i+=128) s_wo[i] = wo[i];
    for (int i=tid; i<4*NC*NC; i+=128) s_w1[i] = w1[i];
    for (int idx=tid; idx<4*NC*NC; idx+=128){
        int j = idx >> 4, i = idx & 15;
        s_w2[idx] = w2[i*(4*NC) + j];
    }
    if (tid < NC){ sg[tid]=g2[tid]; sb[tid]=b2[tid]; }
    __syncthreads();

    int tok = blockIdx.x*128 + tid;
    int b = tok >> 11;
    int t = tok & (NT-1);

    // o16 packed as 8 u64
    u64 o2[8];
    {
        const ulonglong2* p0 = (const ulonglong2*)(g_o + ((size_t)(b*NH+0)*NT + t)*NHS);
        const ulonglong2* p1 = (const ulonglong2*)(g_o + ((size_t)(b*NH+1)*NT + t)*NHS);
        ulonglong2 u0=p0[0], u1=p0[1], u2=p1[0], u3=p1[1];
        o2[0]=u0.x; o2[1]=u0.y; o2[2]=u1.x; o2[3]=u1.y;
        o2[4]=u2.x; o2[5]=u2.y; o2[6]=u3.x; o2[7]=u3.y;
    }

    float xr[NC];
    {
        const float4* x4 = (const float4*)g_x + (size_t)tok*4;
        #pragma unroll
        for (int k=0;k<4;k++){
            float4 v=x4[k];
            xr[4*k]=v.x; xr[4*k+1]=v.y; xr[4*k+2]=v.z; xr[4*k+3]=v.w;
        }
    }

    // Wo projection + residual (f32x2)
    #pragma unroll
    for (int i=0;i<NC;i++){
        const ulonglong2* wr = (const ulonglong2*)(s_wo + i*NC);
        ulonglong2 w0 = wr[0], w1r = wr[1];
        u64 s2 = mul2(o2[0], w0.x);
        s2 = fma2(o2[1], w0.y, s2);
        s2 = fma2(o2[2], w1r.x, s2);
        s2 = fma2(o2[3], w1r.y, s2);
        ulonglong2 w2r = wr[2], w3r = wr[3];
        s2 = fma2(o2[4], w2r.x, s2);
        s2 = fma2(o2[5], w2r.y, s2);
        s2 = fma2(o2[6], w3r.x, s2);
        s2 = fma2(o2[7], w3r.y, s2);
        float2 f = unpack2(s2);
        xr[i] += f.x + f.y;
    }

    // LN2
    float m=0.f;
    #pragma unroll
    for (int c=0;c<NC;c++) m += xr[c];
    m *= (1.f/NC);
    float var=0.f;
    #pragma unroll
    for (int c=0;c<NC;c++){ float d=xr[c]-m; var += d*d; }
    var *= (1.f/NC);
    float inv = rsqrtf(var + EPSF);
    u64 hp[8];
    #pragma unroll
    for (int c=0;c<NC;c+=2){
        float h0 = (xr[c]-m)*inv*sg[c] + sb[c];
        float h1 = (xr[c+1]-m)*inv*sg[c+1] + sb[c+1];
        hp[c>>1] = pack2(h0, h1);
    }

    // MLP (f32x2): d accumulates the residual delta in pairs
    u64 d0=0,d1=0,d2=0,d3=0,d4=0,d5=0,d6=0,d7=0;
    #pragma unroll 4
    for (int j=0;j<4*NC;j++){
        const ulonglong2* wr = (const ulonglong2*)(s_w1 + j*NC);
        ulonglong2 a0 = wr[0], a1 = wr[1], a2 = wr[2], a3 = wr[3];
        u64 y2 = mul2(hp[0], a0.x);
        y2 = fma2(hp[1], a0.y, y2);
        y2 = fma2(hp[2], a1.x, y2);
        y2 = fma2(hp[3], a1.y, y2);
        y2 = fma2(hp[4], a2.x, y2);
        y2 = fma2(hp[5], a2.y, y2);
        y2 = fma2(hp[6], a3.x, y2);
        y2 = fma2(hp[7], a3.y, y2);
        float2 yf = unpack2(y2);
        float yv = fmaxf(yf.x + yf.y, 0.f);
        u64 yy = pack2(yv, yv);
        const ulonglong2* cr = (const ulonglong2*)(s_w2 + j*NC);
        ulonglong2 c0 = cr[0], c1 = cr[1], c2 = cr[2], c3 = cr[3];
        d0 = fma2(yy, c0.x, d0);
        d1 = fma2(yy, c0.y, d1);
        d2 = fma2(yy, c1.x, d2);
        d3 = fma2(yy, c1.y, d3);
        d4 = fma2(yy, c2.x, d4);
        d5 = fma2(yy, c2.y, d5);
        d6 = fma2(yy, c3.x, d6);
        d7 = fma2(yy, c3.y, d7);
    }
    float2 e0=unpack2(d0), e1=unpack2(d1), e2=unpack2(d2), e3=unpack2(d3);
    float2 e4=unpack2(d4), e5=unpack2(d5), e6=unpack2(d6), e7=unpack2(d7);
    xr[0]+=e0.x; xr[1]+=e0.y; xr[2]+=e1.x; xr[3]+=e1.y;
    xr[4]+=e2.x; xr[5]+=e2.y; xr[6]+=e3.x; xr[7]+=e3.y;
    xr[8]+=e4.x; xr[9]+=e4.y; xr[10]+=e5.x; xr[11]+=e5.y;
    xr[12]+=e6.x; xr[13]+=e6.y; xr[14]+=e7.x; xr[15]+=e7.y;

    float4* xo = (float4*)g_x + (size_t)tok*4;
    #pragma unroll
    for (int k=0;k<4;k++)
        xo[k] = make_float4(xr[4*k], xr[4*k+1], xr[4*k+2], xr[4*k+3]);
}

// ---------------------------------------------------------------------------
// 4) h = LNf(x); logits = h @ tok_emb^T.
//    Block = 256 threads, 16 tokens/block; te row registered once per thread.
// ---------------------------------------------------------------------------
__global__ void __launch_bounds__(NV) head_kernel(const float* __restrict__ te,
                                                  const float* __restrict__ gf,
                                                  const float* __restrict__ bf,
                                                  float* __restrict__ out){
    int tid  = threadIdx.x;
    int warp = tid >> 5, lane = tid & 31;
    int tok0 = blockIdx.x * 16;
    __shared__ __align__(16) float hs[16][NC];

    // warp w handles tokens 2w (lanes 0-15) and 2w+1 (lanes 16-31), width-16 shuffles
    {
        int sub = lane >> 4;           // 0 or 1
        int c   = lane & 15;
        int tok = tok0 + warp*2 + sub;
        float val = g_x[(size_t)tok*NC + c];
        float s = val;
        #pragma unroll
        for (int o=8;o>0;o>>=1) s += __shfl_xor_sync(0xffffffffu, s, o, 16);
        float m = s * (1.f/NC);
        float d = val - m;
        float vv = d*d;
        #pragma unroll
        for (int o=8;o>0;o>>=1) vv += __shfl_xor_sync(0xffffffffu, vv, o, 16);
        float inv = rsqrtf(vv*(1.f/NC) + EPSF);
        hs[warp*2+sub][c] = d*inv*gf[c] + bf[c];
    }
    __syncthreads();

    int v = tid;
    const ulonglong2* tr = (const ulonglong2*)te + v*4;
    ulonglong2 t0 = tr[0], t1 = tr[1], t2 = tr[2], t3 = tr[3];

    #pragma unroll 4
    for (int k=0;k<16;k++){
        const ulonglong2* hp = (const ulonglong2*)hs[k];
        ulonglong2 h0 = hp[0], h1 = hp[1];
        u64 s2 = mul2(h0.x, t0.x);
        s2 = fma2(h0.y, t0.y, s2);
        s2 = fma2(h1.x, t1.x, s2);
        s2 = fma2(h1.y, t1.y, s2);
        ulonglong2 h2 = hp[2], h3 = hp[3];
        s2 = fma2(h2.x, t2.x, s2);
        s2 = fma2(h2.y, t2.y, s2);
        s2 = fma2(h3.x, t3.x, s2);
        s2 = fma2(h3.y, t3.y, s2);
        float2 f = unpack2(s2);
        out[(size_t)(tok0+k)*NV + v] = f.x + f.y;
    }
}

// ---------------------------------------------------------------------------
extern "C" void kernel_launch(void* const* d_in, const int* in_sizes, int n_in,
                              void* d_out, int out_size){
    const int*   idx  = (const int*)  d_in[0];
    const float* te   = (const float*)d_in[1];
    const float* pe   = (const float*)d_in[2];
    const float* wq   = (const float*)d_in[3];
    const float* wk   = (const float*)d_in[4];
    const float* wv   = (const float*)d_in[5];
    const float* wo   = (const float*)d_in[6];
    const float* ln1g = (const float*)d_in[7];
    const float* ln1b = (const float*)d_in[8];
    const float* ln2g = (const float*)d_in[9];
    const float* ln2b = (const float*)d_in[10];
    const float* w1   = (const float*)d_in[11];
    const float* w2   = (const float*)d_in[12];
    const float* lnfg = (const float*)d_in[13];
    const float* lnfb = (const float*)d_in[14];
    float* out = (float*)d_out;

    for (int l=0; l<NL; l++){
        qkv_kernel<<<NTOK/128, 128>>>(wq + l*NH*NC*NHS, wk + l*NH*NC*NHS,
                                      wv + l*NH*NC*NHS, ln1g + l*NC, ln1b + l*NC,
                                      idx, te, pe, (l==0) ? 1 : 0);
        dim3 ag(NB*NH, 4);
        attn_kernel<<<ag, 256>>>();
        post_kernel<<<NTOK/128, 128>>>(wo + l*NC*NC, ln2g + l*NC, ln2b + l*NC,
                                       w1 + l*4*NC*NC, w2 + l*4*NC*NC);
    }
    head_kernel<<<NTOK/16, NV>>>(te, lnfg, lnfb, out);
}